// round 14
// baseline (speedup 1.0000x reference)
#include <cuda_runtime.h>
#include <cstdint>

// ---------------- problem constants ----------------
#define NPC   8000            // 64000/8 render points
#define NREF  10000           // 80000/8 ref points
#define NQ    (NPC + NREF)    // 18000 total queries
#define G     32              // grid resolution
#define NC    (G * G)         // 1024 cells
#define CELL  (1.0f / 32.0f)

#define NB    36              // blocks (<=148 -> all resident, spin-safe)
#define NT    512             // threads per block; NB*NT = 18432 >= NQ

// ---------------- device scratch (no cudaMalloc allowed) ----------------
// Zero at module load; final block re-zeroes control words each run so graph
// replays are deterministic.
__device__ float2   g_pcSort[NPC];
__device__ float2   g_refSort[NREF];
__device__ int      g_pcStart[NC + 1];
__device__ int      g_refStart[NC + 1];
__device__ float    g_sums[2];     // must be 0 at run start
__device__ unsigned g_bar;         // must be 0 at run start
__device__ unsigned g_done;        // must be 0 at run start

static __device__ __forceinline__ int cellOf(float v) {
    int c = (int)(v * (float)G);
    return c < 0 ? 0 : (c > G - 1 ? G - 1 : c);
}

static __device__ __forceinline__ void bar_arrive(unsigned* p) {
    asm volatile("red.release.gpu.global.add.u32 [%0], 1;" :: "l"(p) : "memory");
}
static __device__ __forceinline__ unsigned ld_acq(const unsigned* p) {
    unsigned v;
    asm volatile("ld.acquire.gpu.global.u32 %0, [%1];" : "=r"(v) : "l"(p) : "memory");
    return v;
}
// CG-style grid barrier (proven in R13): syncthreads orders block writes
// before t0's release arrival; acquire spin + syncthreads publishes.
static __device__ __forceinline__ void gridBarrier(unsigned* bar) {
    __syncthreads();
    if (threadIdx.x == 0) {
        bar_arrive(bar);
        while (ld_acq(bar) < (unsigned)NB) { }
    }
    __syncthreads();
}

static __device__ __forceinline__ unsigned ticket_release(unsigned* p) {
    unsigned old;
    asm volatile("atom.release.gpu.global.add.u32 %0, [%1], 1;"
                 : "=r"(old) : "l"(p) : "memory");
    return old;
}

// ---------------------------------------------------------------------------
// Grid-NN d^2 (proven exact in R12/R13): 3x3 neighborhood (each row of 3
// cells = one contiguous sorted range), then expanding Chebyshev rings until
// best <= (r*CELL)^2.
// ---------------------------------------------------------------------------
static __device__ float nnDist2(float2 q, const float2* __restrict__ pts,
                                const int* __restrict__ starts) {
    int cx = cellOf(q.x), cy = cellOf(q.y);
    float best = 3.4e38f;

    int x0 = max(cx - 1, 0), x1 = min(cx + 1, G - 1);
    int y0 = max(cy - 1, 0), y1 = min(cy + 1, G - 1);
    for (int yy = y0; yy <= y1; yy++) {
        int s = starts[yy * G + x0], e = starts[yy * G + x1 + 1];
        for (int k = s; k < e; k++) {
            float2 p = pts[k];
            float dx = q.x - p.x, dy = q.y - p.y;
            best = fminf(best, dx * dx + dy * dy);
        }
    }

    int r = 1;
    while (best > ((float)r * CELL) * ((float)r * CELL) && r < G) {
        r++;
        int xa = cx - r, xb = cx + r, ya = cy - r, yb = cy + r;
        int cxa = max(xa, 0), cxb = min(xb, G - 1);
        if (ya >= 0) {
            int s = starts[ya * G + cxa], e = starts[ya * G + cxb + 1];
            for (int k = s; k < e; k++) {
                float2 p = pts[k];
                float dx = q.x - p.x, dy = q.y - p.y;
                best = fminf(best, dx * dx + dy * dy);
            }
        }
        if (yb <= G - 1) {
            int s = starts[yb * G + cxa], e = starts[yb * G + cxb + 1];
            for (int k = s; k < e; k++) {
                float2 p = pts[k];
                float dx = q.x - p.x, dy = q.y - p.y;
                best = fminf(best, dx * dx + dy * dy);
            }
        }
        int cya = max(ya + 1, 0), cyb = min(yb - 1, G - 1);
        for (int yy = cya; yy <= cyb; yy++) {
            if (xa >= 0) {
                int s = starts[yy * G + xa], e = starts[yy * G + xa + 1];
                for (int k = s; k < e; k++) {
                    float2 p = pts[k];
                    float dx = q.x - p.x, dy = q.y - p.y;
                    best = fminf(best, dx * dx + dy * dy);
                }
            }
            if (xb <= G - 1) {
                int s = starts[yy * G + xb], e = starts[yy * G + xb + 1];
                for (int k = s; k < e; k++) {
                    float2 p = pts[k];
                    float dx = q.x - p.x, dy = q.y - p.y;
                    best = fminf(best, dx * dx + dy * dy);
                }
            }
        }
    }
    return best;
}

// ---------------------------------------------------------------------------
// Single fused kernel:
//   blocks 0/1: in-block grid build (smem count -> smem scan -> scatter)
//   grid barrier (the only one)
//   all blocks: warp-coherent NN search over the SORTED point order + ticket
// ---------------------------------------------------------------------------
__global__ void __launch_bounds__(NT) k_all(const float* __restrict__ in0,
                                            const float* __restrict__ in1,
                                            float* __restrict__ out) {
    __shared__ int   scnt[NC];      // counts, then cur cursors
    __shared__ int   sstart[NC + 1];
    __shared__ int   sscan[NT];
    __shared__ float sred[32];
    __shared__ int   sflag;

    int blk = blockIdx.x, t = threadIdx.x;

    // ---- Phase 1: blocks 0/1 each build one grid structure in-block ----
    if (blk < 2) {
        const float* src   = blk ? in0 : in1;            // blk0: ref, blk1: pc
        const int    n     = blk ? NPC : NREF;
        const float  D     = blk ? (63999.0f / 7999.0f) : (79999.0f / 9999.0f);
        float2*      dst   = blk ? g_pcSort : g_refSort;
        int*         gSt   = blk ? g_pcStart : g_refStart;

        for (int i = t; i < NC; i += NT) scnt[i] = 0;
        __syncthreads();

        // count (gather fp32-linspace-trunc indices arithmetically)
        for (int k = t; k < n; k += NT) {
            int si = (int)((float)k * D);
            float x = src[2 * si], y = src[2 * si + 1];
            atomicAdd(&scnt[cellOf(y) * G + cellOf(x)], 1);
        }
        __syncthreads();

        // exclusive scan of 1024 cells: 2 cells/thread + Hillis-Steele(512)
        {
            int b2 = t * 2;
            int v0 = scnt[b2], v1 = scnt[b2 + 1];
            int tot = v0 + v1;
            sscan[t] = tot;
            __syncthreads();
#pragma unroll
            for (int off = 1; off < NT; off <<= 1) {
                int u = (t >= off) ? sscan[t - off] : 0;
                __syncthreads();
                sscan[t] += u;
                __syncthreads();
            }
            int e0 = sscan[t] - tot;
            sstart[b2] = e0;
            sstart[b2 + 1] = e0 + v0;
            if (t == NT - 1) sstart[NC] = sscan[t];
        }
        __syncthreads();
        // publish starts to global; reset cursors
        for (int i = t; i < NC; i += NT) { gSt[i] = sstart[i]; scnt[i] = sstart[i]; }
        if (t == 0) gSt[NC] = sstart[NC];
        __syncthreads();

        // scatter (re-gather; source is L2/L1 hot)
        for (int k = t; k < n; k += NT) {
            int si = (int)((float)k * D);
            float x = src[2 * si], y = src[2 * si + 1];
            int pos = atomicAdd(&scnt[cellOf(y) * G + cellOf(x)], 1);
            dst[pos] = make_float2(x, y);
        }
    }

    gridBarrier(&g_bar);   // the only grid-wide barrier

    // ---- Phase 2: warp-coherent search over sorted order ----
    int gtid = blk * NT + t;
    float s1 = 0.0f, s2 = 0.0f;
    if (gtid < NPC) {
        s1 = sqrtf(nnDist2(g_pcSort[gtid], g_refSort, g_refStart));
    } else if (gtid < NQ) {
        s2 = sqrtf(nnDist2(g_refSort[gtid - NPC], g_pcSort, g_pcStart));
    }

#pragma unroll
    for (int off = 16; off > 0; off >>= 1) {
        s1 += __shfl_down_sync(0xFFFFFFFFu, s1, off);
        s2 += __shfl_down_sync(0xFFFFFFFFu, s2, off);
    }
    int w = t >> 5;                       // 16 warps
    if ((t & 31) == 0) { sred[2 * w] = s1; sred[2 * w + 1] = s2; }
    __syncthreads();
    if (t == 0) {
        float b1 = 0.0f, b2 = 0.0f;
#pragma unroll
        for (int k = 0; k < 16; k++) { b1 += sred[2 * k]; b2 += sred[2 * k + 1]; }
        if (b1 != 0.0f) atomicAdd(&g_sums[0], b1);
        if (b2 != 0.0f) atomicAdd(&g_sums[1], b2);
        sflag = (ticket_release(&g_done) == (unsigned)(NB - 1));
    }
    __syncthreads();
    if (!sflag) return;

    // ---- last surviving block: finalize + reset control for graph replay ----
    if (t == 0) {
        asm volatile("fence.acq_rel.gpu;" ::: "memory");
        float S1, S2;
        asm volatile("ld.global.cv.f32 %0, [%1];" : "=f"(S1) : "l"(&g_sums[0]));
        asm volatile("ld.global.cv.f32 %0, [%1];" : "=f"(S2) : "l"(&g_sums[1]));
        out[0] = (S1 * (1.0f / NPC) + S2 * (1.0f / NREF)) * 0.5f;
        g_sums[0] = 0.0f; g_sums[1] = 0.0f;
        g_done = 0u;
        g_bar  = 0u;
    }
}

extern "C" void kernel_launch(void* const* d_in, const int* in_sizes, int n_in,
                              void* d_out, int out_size) {
    const float* in0 = (const float*)d_in[0];   // img_render_points
    const float* in1 = (const float*)d_in[1];   // ref point cloud
    float* out = (float*)d_out;

    k_all<<<NB, NT>>>(in0, in1, out);
}